// round 15
// baseline (speedup 1.0000x reference)
#include <cuda_runtime.h>
#include <cuda_fp16.h>
#include <cstdint>
#include <math.h>

// ---------------- problem constants ----------------
#define Bsz   1024
#define Tlen  80
#define Dd    512
#define Cc    78
#define Mrows (Bsz*Tlen)          // 81920
#define BLANKI 77
#define PRED  30
#define LOGITS_ELEMS ((size_t)Mrows * Cc)

// ---------------- tiling (R13-proven shape; W split fused in-loop) ----------------
#define BK    32                  // K per chunk (2 mma k-steps)
#define NCH   (Dd/BK)             // 16 chunks
#define AROW  40                  // fp16 row stride (32 data + 8 pad; 80B, 16B-aligned)
#define BROW  40
#define APL   (128*AROW*2)        // A plane bytes = 10240
#define BPL   (80*BROW*2)         // B plane bytes = 6400
#define BOFF  (2*APL)             // 20480
#define STAGE (BOFF + 2*BPL)      // 33280
#define SMEM_BYTES (2*STAGE)      // 66560 (>= 128*84*4 = 43008 epilogue bytes); 2 CTAs/SM
#define LP    84                  // epilogue logits row stride (floats)
#define NPAIRS (16*Cc)            // (k2, n) items per chunk = 1248

// ---------------- device scratch (static, no runtime alloc) ----------------
__device__ int g_best[Mrows];

// ---------------- helpers ----------------
// paired fp16 2-limb split: (x,y) -> 2 packed half2 limbs
__device__ __forceinline__ void split2x2(float x, float y,
                                         uint32_t& p0, uint32_t& p1) {
    __half2 h0 = __float22half2_rn(make_float2(x, y));
    float2 f0 = __half22float2(h0);
    __half2 h1 = __float22half2_rn(make_float2(x - f0.x, y - f0.y));
    p0 = *reinterpret_cast<uint32_t*>(&h0);
    p1 = *reinterpret_cast<uint32_t*>(&h1);
}

__device__ __forceinline__ void mma16816(float c[4], const uint32_t a[4],
                                         const uint32_t b[2]) {
    asm volatile(
        "mma.sync.aligned.m16n8k16.row.col.f32.f16.f16.f32 "
        "{%0,%1,%2,%3}, {%4,%5,%6,%7}, {%8,%9}, {%0,%1,%2,%3};"
        : "+f"(c[0]), "+f"(c[1]), "+f"(c[2]), "+f"(c[3])
        : "r"(a[0]), "r"(a[1]), "r"(a[2]), "r"(a[3]), "r"(b[0]), "r"(b[1]));
}

#define LDMX4(r, addr) \
    asm volatile("ldmatrix.sync.aligned.m8n8.x4.shared.b16 {%0,%1,%2,%3}, [%4];" \
        : "=r"((r)[0]), "=r"((r)[1]), "=r"((r)[2]), "=r"((r)[3]) : "r"(addr))
#define LDMX4P(r0, r1, addr) \
    asm volatile("ldmatrix.sync.aligned.m8n8.x4.shared.b16 {%0,%1,%2,%3}, [%4];" \
        : "=r"((r0)[0]), "=r"((r0)[1]), "=r"((r1)[0]), "=r"((r1)[1]) : "r"(addr))
#define LDMX2(r, addr) \
    asm volatile("ldmatrix.sync.aligned.m8n8.x2.shared.b16 {%0,%1}, [%2];" \
        : "=r"((r)[0]), "=r"((r)[1]) : "r"(addr))

// ---------------- fused GEMM (in-loop W transpose/split) + softmax + argmax ----------------
// CTA tile 128x80, 8 warps as (wm 0..3) x (wn 0..1): warp tile 32x40.
// Per k16-step: 3 limb passes {a0b0, a1b0, a0b1} (a1b1 ~2^-22, dropped).
__global__ __launch_bounds__(256, 2)
void gemm_mma_kernel(const float* __restrict__ feat,
                     const float* __restrict__ Wm,
                     const float* __restrict__ bias,
                     float* __restrict__ out)
{
    extern __shared__ char dsm[];
    __shared__ float bias_s[80];
    __shared__ float rinv_s[128];

    const int t    = threadIdx.x;
    const int lane = t & 31;
    const int wid  = t >> 5;
    const int wm   = wid & 3;
    const int wn   = wid >> 2;
    const int gID  = lane >> 2;
    const int tid4 = lane & 3;
    const int m0   = blockIdx.x * 128;
    const uint32_t dsmu = (uint32_t)__cvta_generic_to_shared(dsm);

    if (t < 80) bias_s[t] = (t < Cc) ? bias[t] : 0.0f;

    // ldmatrix per-lane address offsets (within plane)
    const uint32_t aoff0 = (uint32_t)((wm * 32 + (lane & 15)) * (AROW * 2) + (lane >> 4) * 16);
    const uint32_t aoff1 = aoff0 + 16 * (AROW * 2);
    const uint32_t boff0 = (uint32_t)((wn * 40 + (lane >> 4) * 8 + (lane & 7)) * (BROW * 2)
                                      + ((lane >> 3) & 1) * 16);
    const uint32_t boff2 = boff0 + 16 * (BROW * 2);
    const uint32_t boff4 = (uint32_t)((wn * 40 + 32 + (lane & 7)) * (BROW * 2)
                                      + ((lane >> 3) & 1) * 16);

    float acc[2][5][4];
#pragma unroll
    for (int i = 0; i < 2; i++)
#pragma unroll
        for (int j = 0; j < 5; j++)
#pragma unroll
            for (int q = 0; q < 4; q++) acc[i][j][q] = 0.0f;

    const float* featb = feat + (size_t)m0 * Dd;

    // per-thread (k2, n) items for the W transpose/split (5 per thread)
    int wk2[5], wn_[5];
#pragma unroll
    for (int i = 0; i < 5; i++) {
        const int idx = t + 256 * i;
        wk2[i] = (idx < NPAIRS) ? idx / Cc : -1;
        wn_[i] = idx - wk2[i] * Cc;
    }

    // ---- A store: split fp32 float4 -> 2 fp16 planes ----
    auto storeA = [&](char* aB, int fidx, float4 v) {
        const int r = fidx >> 3, q = fidx & 7;       // 8 float4 per 32-float row
        const int off = r * (AROW * 2) + q * 8;
        uint32_t p0a, p1a, p0b, p1b;
        split2x2(v.x, v.y, p0a, p1a);
        split2x2(v.z, v.w, p0b, p1b);
        *(uint32_t*)(aB + 0 * APL + off)     = p0a;
        *(uint32_t*)(aB + 0 * APL + off + 4) = p0b;
        *(uint32_t*)(aB + 1 * APL + off)     = p1a;
        *(uint32_t*)(aB + 1 * APL + off + 4) = p1b;
    };
    // ---- B store: split a k-pair of W^T into both limb planes ----
    auto storeB = [&](char* bB, int i, float w0, float w1) {
        if (wk2[i] >= 0) {
            const int off = wn_[i] * (BROW * 2) + wk2[i] * 4;
            uint32_t p0, p1;
            split2x2(w0, w1, p0, p1);
            *(uint32_t*)(bB + 0 * BPL + off) = p0;
            *(uint32_t*)(bB + 1 * BPL + off) = p1;
        }
    };

    // ---- prologue: chunk 0 (direct load + split) ----
    {
#pragma unroll
        for (int i = 0; i < 4; i++) {
            const int fidx = t + 256 * i;           // 0..1023
            const int r = fidx >> 3, q = fidx & 7;
            float4 v = *reinterpret_cast<const float4*>(featb + (size_t)r * Dd + q * 4);
            storeA(dsm, fidx, v);
        }
#pragma unroll
        for (int i = 0; i < 5; i++) {
            if (wk2[i] >= 0) {
                const float w0 = Wm[(size_t)(2 * wk2[i])     * Cc + wn_[i]];
                const float w1 = Wm[(size_t)(2 * wk2[i] + 1) * Cc + wn_[i]];
                storeB(dsm + BOFF, i, w0, w1);
            }
        }
    }
    __syncthreads();

    // ---- main loop: 16 chunks ----
    for (int ch = 0; ch < NCH; ++ch) {
        const int s = ch & 1;
        const uint32_t aBu = dsmu + s * STAGE;
        const uint32_t bBu = aBu + BOFF;

        float4 pf[4];
        float  pw0[5], pw1[5];
        if (ch < NCH - 1) {
            const int kb = (ch + 1) * BK;
#pragma unroll
            for (int i = 0; i < 4; i++) {
                const int fidx = t + 256 * i;
                const int r = fidx >> 3, q = fidx & 7;
                pf[i] = *reinterpret_cast<const float4*>(featb + (size_t)r * Dd + kb + q * 4);
            }
#pragma unroll
            for (int i = 0; i < 5; i++) {
                if (wk2[i] >= 0) {
                    pw0[i] = Wm[(size_t)(kb + 2 * wk2[i])     * Cc + wn_[i]];
                    pw1[i] = Wm[(size_t)(kb + 2 * wk2[i] + 1) * Cc + wn_[i]];
                }
            }
        }

        // ---- 2 k-steps of 3-pass fp16 limb mma (ldmatrix fragments) ----
#pragma unroll
        for (int k0 = 0; k0 < 2; k0++) {
            const uint32_t kb2 = k0 * 32;           // 16 fp16 = 32 bytes
            uint32_t afr[2][2][4];
#pragma unroll
            for (int ai = 0; ai < 2; ai++) {
                LDMX4(afr[ai][0], aBu + ai * APL + aoff0 + kb2);
                LDMX4(afr[ai][1], aBu + ai * APL + aoff1 + kb2);
            }
#pragma unroll
            for (int bj = 0; bj < 2; bj++) {
                uint32_t b[5][2];
                LDMX4P(b[0], b[1], bBu + bj * BPL + boff0 + kb2);
                LDMX4P(b[2], b[3], bBu + bj * BPL + boff2 + kb2);
                LDMX2(b[4],        bBu + bj * BPL + boff4 + kb2);
#pragma unroll
                for (int ai = 0; ai <= 1 - bj; ai++)
#pragma unroll
                    for (int i = 0; i < 2; i++)
#pragma unroll
                        for (int j = 0; j < 5; j++)
                            mma16816(acc[i][j], afr[ai][i], b[j]);
            }
        }

        if (ch < NCH - 1) {
            char* aN = dsm + (s ^ 1) * STAGE;
#pragma unroll
            for (int i = 0; i < 4; i++) storeA(aN, t + 256 * i, pf[i]);
#pragma unroll
            for (int i = 0; i < 5; i++) storeB(aN + BOFF, i, pw0[i], pw1[i]);
        }
        __syncthreads();
    }

    // ---- stage logits (+bias) to smem ----
    float* L = (float*)dsm;
#pragma unroll
    for (int i = 0; i < 2; i++)
#pragma unroll
        for (int j = 0; j < 5; j++) {
            const int r0 = wm * 32 + i * 16 + gID;
            const int c0 = wn * 40 + j * 8 + tid4 * 2;
            L[r0 * LP + c0]           = acc[i][j][0] + bias_s[c0];
            L[r0 * LP + c0 + 1]       = acc[i][j][1] + bias_s[c0 + 1];
            L[(r0 + 8) * LP + c0]     = acc[i][j][2] + bias_s[c0];
            L[(r0 + 8) * LP + c0 + 1] = acc[i][j][3] + bias_s[c0 + 1];
        }
    __syncthreads();

    // ---- softmax + argmax: 2 threads per row (39 cols each) ----
    {
        const int r = t >> 1, h = t & 1;
        const int cb = h * 39;
        float mx = -1e30f; int am = 127;
        for (int c = 0; c < 39; c++) {
            float v = L[r * LP + cb + c];
            if (v > mx) { mx = v; am = cb + c; }
        }
        float omx = __shfl_xor_sync(0xFFFFFFFFu, mx, 1);
        int   oam = __shfl_xor_sync(0xFFFFFFFFu, am, 1);
        if (omx > mx || (omx == mx && oam < am)) { mx = omx; am = oam; }
        float ssum = 0.0f;
        for (int c = 0; c < 39; c++) {
            float e = __expf(L[r * LP + cb + c] - mx);
            L[r * LP + cb + c] = e;
            ssum += e;
        }
        ssum += __shfl_xor_sync(0xFFFFFFFFu, ssum, 1);
        if (h == 0) {
            rinv_s[r] = __frcp_rn(ssum);
            g_best[m0 + r] = am;
        }
    }
    __syncthreads();

    // ---- coalesced softmax prob writes ----
    for (int idx = t; idx < 128 * Cc; idx += 256) {
        const int r = idx / Cc, c = idx - r * Cc;
        out[(size_t)(m0 + r) * Cc + c] = L[r * LP + c] * rinv_s[r];
    }
}

// ---------------- CTC greedy collapse (warp-ballot, proven) ----------------
__global__ __launch_bounds__(256)
void decode_kernel(float* __restrict__ out, size_t out_elems)
{
    const int warp = (blockIdx.x * blockDim.x + threadIdx.x) >> 5;
    const int lane = threadIdx.x & 31;
    if (warp >= Bsz) return;

    size_t obase = LOGITS_ELEMS + (size_t)warp * PRED;
    if (obase + PRED > out_elems) return;
    float* lab = out + obase;

    if (lane < PRED) lab[lane] = -1.0f;
    __syncwarp();

    const int* row = g_best + (size_t)warp * Tlen;
    int prefix = 0;
    int carry  = -1;
#pragma unroll
    for (int seg = 0; seg < 3; seg++) {
        const int idx = seg * 32 + lane;
        const bool valid = (idx < Tlen);
        int v = valid ? row[idx] : BLANKI;
        int prev = __shfl_up_sync(0xFFFFFFFFu, v, 1);
        if (lane == 0) prev = carry;
        const bool keep = valid && (v != BLANKI) && (v != prev);
        const unsigned mask = __ballot_sync(0xFFFFFFFFu, keep);
        const int pos = prefix + __popc(mask & ((1u << lane) - 1u));
        if (keep && pos < PRED) lab[pos] = (float)v;
        prefix += __popc(mask);
        carry = __shfl_sync(0xFFFFFFFFu, v, 31);
    }
}

// ---------------- launch ----------------
extern "C" void kernel_launch(void* const* d_in, const int* in_sizes, int n_in,
                              void* d_out, int out_size)
{
    const float* feat = (const float*)d_in[0];  // [1024,80,512]
    const float* Wm   = (const float*)d_in[1];  // [512,78]
    const float* bias = (const float*)d_in[2];  // [78]
    float* out = (float*)d_out;

    cudaFuncSetAttribute(gemm_mma_kernel,
                         cudaFuncAttributeMaxDynamicSharedMemorySize, SMEM_BYTES);

    gemm_mma_kernel<<<Mrows / 128, 256, SMEM_BYTES>>>(feat, Wm, bias, out);
    decode_kernel<<<(Bsz * 32) / 256, 256>>>(out, (size_t)out_size);
}